// round 1
// baseline (speedup 1.0000x reference)
#include <cuda_runtime.h>
#include <cstdint>

// Problem constants (B=1)
#define S_LEN 2048
#define D_DIM 128
#define HQ 32
#define HKV 8
#define GROUP 4

#define BM 64          // Q rows per CTA
#define BN 64          // KV rows per tile
#define NTHREADS 256

// ---------------- scratch (device globals; no allocation allowed) -------------
__device__ float g_Qt[(size_t)HQ * D_DIM * S_LEN];   // [h][d][s]  (k-major Q)
__device__ float g_Kt[(size_t)HKV * D_DIM * S_LEN];  // [h][d][s]  (k-major K)

// ---------------- helpers ----------------------------------------------------
__device__ __forceinline__ float ex2f(float x) {
    float y;
    asm("ex2.approx.f32 %0, %1;" : "=f"(y) : "f"(x));
    return y;
}

__device__ __forceinline__ void cpa16(float* smem_dst, const float* gmem_src) {
    uint32_t s = (uint32_t)__cvta_generic_to_shared(smem_dst);
    asm volatile("cp.async.cg.shared.global [%0], [%1], 16;\n" :: "r"(s), "l"(gmem_src));
}
__device__ __forceinline__ void cpa_commit() {
    asm volatile("cp.async.commit_group;\n" ::: "memory");
}
__device__ __forceinline__ void cpa_wait1() {
    asm volatile("cp.async.wait_group 1;\n" ::: "memory");
}
__device__ __forceinline__ void cpa_wait0() {
    asm volatile("cp.async.wait_group 0;\n" ::: "memory");
}

// ---------------- transpose [H][S][D] -> [H][D][S] ----------------------------
// which: 0 -> g_Qt, 1 -> g_Kt
__global__ void transpose_kernel(const float* __restrict__ in, int which) {
    __shared__ float tile[32][33];
    int h  = blockIdx.z;
    int d0 = blockIdx.x * 32;
    int s0 = blockIdx.y * 32;
    const float* inh = in + (size_t)h * S_LEN * D_DIM;
    float* outh = (which == 0 ? g_Qt : g_Kt) + (size_t)h * D_DIM * S_LEN;
    int tx = threadIdx.x, ty = threadIdx.y;
#pragma unroll
    for (int i = 0; i < 32; i += 8)
        tile[ty + i][tx] = inh[(size_t)(s0 + ty + i) * D_DIM + d0 + tx];
    __syncthreads();
#pragma unroll
    for (int i = 0; i < 32; i += 8)
        outh[(size_t)(d0 + ty + i) * S_LEN + s0 + tx] = tile[tx][ty + i];
}

// ---------------- flash attention mainloop ------------------------------------
// Smem layout (floats):
//   Qs   [128][64]           @ 0        (8192)
//   Ks   2 x [128][64]       @ 8192     (16384)
//   Vs   2 x [64][128]       @ 24576    (16384)
//   Ss   [64][64]            @ 40960    (4096)
//   rowm [64] rowl [64] rowa [64]  @ 45056
#define SM_Q   0
#define SM_K   8192
#define SM_V   24576
#define SM_S   40960
#define SM_ST  45056
#define SMEM_FLOATS (SM_ST + 192)
#define SMEM_BYTES  (SMEM_FLOATS * 4)

__global__ void __launch_bounds__(NTHREADS, 1)
attn_kernel(const float* __restrict__ Vg, float* __restrict__ out) {
    extern __shared__ float sm[];
    float* Qs   = sm + SM_Q;
    float* Ks   = sm + SM_K;
    float* Vs   = sm + SM_V;
    float* Ss   = sm + SM_S;
    float* rowm = sm + SM_ST;
    float* rowl = rowm + 64;
    float* rowa = rowl + 64;

    const int t   = threadIdx.x;
    const int h   = blockIdx.y;
    const int qt  = (int)gridDim.x - 1 - (int)blockIdx.x;  // longest first
    const int kvh = h / GROUP;

    const float* Qtb = g_Qt + (size_t)h   * D_DIM * S_LEN + qt * BM; // row d: stride S_LEN
    const float* Ktb = g_Kt + (size_t)kvh * D_DIM * S_LEN;
    const float* Vb  = Vg   + (size_t)kvh * S_LEN * D_DIM;

    // QK mapping: 4x4 per thread on 16x16 thread grid
    const int ty = t >> 4;       // 0..15 -> rows 4*ty..
    const int tx = t & 15;       // 0..15 -> cols 4*tx..
    // PV mapping: 8 rows x 4 d-cols per thread
    const int rg = t >> 5;       // 0..7  -> rows 8*rg..
    const int cg = t & 31;       // 0..31 -> d cols 4*cg..

    if (t < 64) {
        rowm[t] = __int_as_float(0xff800000); // -inf
        rowl[t] = 0.0f;
    }

    // ---- prefetch Q + K0 + V0 (group 0) ----
    {
#pragma unroll
        for (int i = 0; i < 8; ++i) {          // Q tile: [128][64]
            int idx = t + NTHREADS * i;
            int d = idx >> 4, c16 = idx & 15;
            cpa16(Qs + d * BM + c16 * 4, Qtb + (size_t)d * S_LEN + c16 * 4);
        }
#pragma unroll
        for (int i = 0; i < 8; ++i) {          // K tile 0
            int idx = t + NTHREADS * i;
            int d = idx >> 4, c16 = idx & 15;
            cpa16(Ks + d * BM + c16 * 4, Ktb + (size_t)d * S_LEN + c16 * 4);
        }
#pragma unroll
        for (int i = 0; i < 8; ++i) {          // V tile 0 (contiguous 32KB)
            int idx = t + NTHREADS * i;
            cpa16(Vs + idx * 4, Vb + idx * 4);
        }
        cpa_commit();
    }

    float o[8][4];
#pragma unroll
    for (int i = 0; i < 8; ++i)
#pragma unroll
        for (int j = 0; j < 4; ++j) o[i][j] = 0.0f;

    const int nt = qt + 1;
    const float Csc = 0.08838834764831845f * 1.4426950408889634f; // (1/sqrt(128))*log2(e)

    for (int kt = 0; kt < nt; ++kt) {
        const int cur = kt & 1;

        if (kt + 1 < nt) {
            const int nb = (kt + 1) & 1;
            float* Kd = Ks + nb * 8192;
            float* Vd = Vs + nb * 8192;
            const float* Ksrc = Ktb + (kt + 1) * BN;
            const float* Vsrc = Vb + (size_t)(kt + 1) * BN * D_DIM;
#pragma unroll
            for (int i = 0; i < 8; ++i) {
                int idx = t + NTHREADS * i;
                int d = idx >> 4, c16 = idx & 15;
                cpa16(Kd + d * BM + c16 * 4, Ksrc + (size_t)d * S_LEN + c16 * 4);
            }
#pragma unroll
            for (int i = 0; i < 8; ++i) {
                int idx = t + NTHREADS * i;
                cpa16(Vd + idx * 4, Vsrc + idx * 4);
            }
            cpa_commit();
            cpa_wait1();
        } else {
            cpa_wait0();
        }
        __syncthreads();

        const float* Kc = Ks + cur * 8192;
        const float* Vc = Vs + cur * 8192;

        // ---- QK^T: s[4][4] ----
        float s[4][4];
#pragma unroll
        for (int i = 0; i < 4; ++i)
#pragma unroll
            for (int j = 0; j < 4; ++j) s[i][j] = 0.0f;

#pragma unroll 8
        for (int k = 0; k < D_DIM; ++k) {
            float4 qv = *reinterpret_cast<const float4*>(Qs + k * BM + 4 * ty);
            float4 kv = *reinterpret_cast<const float4*>(Kc + k * BN + 4 * tx);
            float qa[4] = {qv.x, qv.y, qv.z, qv.w};
            float ka[4] = {kv.x, kv.y, kv.z, kv.w};
#pragma unroll
            for (int i = 0; i < 4; ++i)
#pragma unroll
                for (int j = 0; j < 4; ++j)
                    s[i][j] += qa[i] * ka[j];
        }

        // scale (+ causal mask on diagonal tile), store to Ss
        const bool diag = (kt == qt);
#pragma unroll
        for (int i = 0; i < 4; ++i) {
            float4 sv;
            float* sp = &sv.x;
#pragma unroll
            for (int j = 0; j < 4; ++j) {
                float v = s[i][j] * Csc;
                if (diag && (4 * tx + j > 4 * ty + i)) v = -1e30f;
                sp[j] = v;
            }
            *reinterpret_cast<float4*>(Ss + (4 * ty + i) * BN + 4 * tx) = sv;
        }
        __syncthreads();

        // ---- online softmax: 4 threads per row, 16 cols each ----
        {
            const int r  = t >> 2;
            const int jj = t & 3;
            float* srow = Ss + r * BN + jj * 16;
            float4 x[4];
#pragma unroll
            for (int u = 0; u < 4; ++u) x[u] = *reinterpret_cast<const float4*>(srow + 4 * u);

            float mx = x[0].x;
#pragma unroll
            for (int u = 0; u < 4; ++u) {
                mx = fmaxf(mx, x[u].x); mx = fmaxf(mx, x[u].y);
                mx = fmaxf(mx, x[u].z); mx = fmaxf(mx, x[u].w);
            }
            mx = fmaxf(mx, __shfl_xor_sync(0xffffffffu, mx, 1));
            mx = fmaxf(mx, __shfl_xor_sync(0xffffffffu, mx, 2));

            const float mold = rowm[r];
            const float mnew = fmaxf(mold, mx);

            float sum = 0.0f;
#pragma unroll
            for (int u = 0; u < 4; ++u) {
                x[u].x = ex2f(x[u].x - mnew); sum += x[u].x;
                x[u].y = ex2f(x[u].y - mnew); sum += x[u].y;
                x[u].z = ex2f(x[u].z - mnew); sum += x[u].z;
                x[u].w = ex2f(x[u].w - mnew); sum += x[u].w;
            }
            sum += __shfl_xor_sync(0xffffffffu, sum, 1);
            sum += __shfl_xor_sync(0xffffffffu, sum, 2);

#pragma unroll
            for (int u = 0; u < 4; ++u) *reinterpret_cast<float4*>(srow + 4 * u) = x[u];

            if (jj == 0) {
                const float alpha = ex2f(mold - mnew);
                rowm[r] = mnew;
                rowa[r] = alpha;
                rowl[r] = rowl[r] * alpha + sum;
            }
        }
        __syncthreads();

        // ---- rescale O, then O += P @ V ----
#pragma unroll
        for (int i = 0; i < 8; ++i) {
            const float a = rowa[8 * rg + i];
            o[i][0] *= a; o[i][1] *= a; o[i][2] *= a; o[i][3] *= a;
        }

#pragma unroll 2
        for (int c0 = 0; c0 < BN; c0 += 4) {
            float4 vv[4];
#pragma unroll
            for (int j = 0; j < 4; ++j)
                vv[j] = *reinterpret_cast<const float4*>(Vc + (c0 + j) * D_DIM + 4 * cg);
#pragma unroll
            for (int i = 0; i < 8; ++i) {
                float4 p = *reinterpret_cast<const float4*>(Ss + (8 * rg + i) * BN + c0);
                o[i][0] += p.x * vv[0].x + p.y * vv[1].x + p.z * vv[2].x + p.w * vv[3].x;
                o[i][1] += p.x * vv[0].y + p.y * vv[1].y + p.z * vv[2].y + p.w * vv[3].y;
                o[i][2] += p.x * vv[0].z + p.y * vv[1].z + p.z * vv[2].z + p.w * vv[3].z;
                o[i][3] += p.x * vv[0].w + p.y * vv[1].w + p.z * vv[2].w + p.w * vv[3].w;
            }
        }
        __syncthreads();
    }

    // ---- epilogue: divide by l, store ----
#pragma unroll
    for (int i = 0; i < 8; ++i) {
        const int row = 8 * rg + i;
        const float inv = 1.0f / rowl[row];
        float4 ov = make_float4(o[i][0] * inv, o[i][1] * inv, o[i][2] * inv, o[i][3] * inv);
        float* dst = out + ((size_t)h * S_LEN + (size_t)qt * BM + row) * D_DIM + 4 * cg;
        *reinterpret_cast<float4*>(dst) = ov;
    }
}

// ---------------- launch ------------------------------------------------------
extern "C" void kernel_launch(void* const* d_in, const int* in_sizes, int n_in,
                              void* d_out, int out_size) {
    const float* q = (const float*)d_in[0];
    const float* k = (const float*)d_in[1];
    const float* v = (const float*)d_in[2];
    float* out = (float*)d_out;

    // Pre-transpose Q and K to k-major [h][d][s]
    transpose_kernel<<<dim3(D_DIM / 32, S_LEN / 32, HQ),  dim3(32, 8)>>>(q, 0);
    transpose_kernel<<<dim3(D_DIM / 32, S_LEN / 32, HKV), dim3(32, 8)>>>(k, 1);

    cudaFuncSetAttribute(attn_kernel, cudaFuncAttributeMaxDynamicSharedMemorySize, SMEM_BYTES);
    attn_kernel<<<dim3(S_LEN / BM, HQ), NTHREADS, SMEM_BYTES>>>(v, out);
}